// round 4
// baseline (speedup 1.0000x reference)
#include <cuda_runtime.h>
#include <cuda_bf16.h>
#include <cstdint>

// Problem constants
#define VOCAB 96
#define TT 16
#define EE 64
#define HH 4
#define KK 16
#define LL 4
#define BB 16384

#define G 4                 // sequences per CTA
#define ROWS (G*TT)         // 64 activation rows per CTA
#define XS_STRIDE 68        // padded row stride (floats, 16B aligned)
#define NTHREADS 256

typedef unsigned long long ull;

// ---------- packed f32x2 helpers ----------
__device__ __forceinline__ ull pack2(float x, float y) {
    ull r;
    asm("mov.b64 %0, {%1, %2};" : "=l"(r) : "r"(__float_as_uint(x)), "r"(__float_as_uint(y)));
    return r;
}
__device__ __forceinline__ void unpack2(ull p, float& x, float& y) {
    unsigned int a, b;
    asm("mov.b64 {%0, %1}, %2;" : "=r"(a), "=r"(b) : "l"(p));
    x = __uint_as_float(a); y = __uint_as_float(b);
}
__device__ __forceinline__ void fma2(ull& d, ull a, ull b) {
    asm("fma.rn.f32x2 %0, %1, %2, %3;" : "=l"(d) : "l"(a), "l"(b), "l"(d));
}

// ---------- GEMM [64 x 64] * [64 x 64]: A stride 68, W stride 64 ----------
// 256 threads: rb = tid>>4 (4 rows each), cb = tid&15 (4 cols each).
template <class F>
__device__ __forceinline__ void gemm64(const float* __restrict__ A,
                                       const float* __restrict__ W, F epi) {
    const int tid = threadIdx.x;
    const int cb = tid & 15, rb = tid >> 4;
    ull a01[4], a23[4];
#pragma unroll
    for (int i = 0; i < 4; i++) { a01[i] = 0ull; a23[i] = 0ull; }
    const float* Arow = A + rb * 4 * XS_STRIDE;
    const float* Wp = W + cb * 4;
#pragma unroll 4
    for (int e0 = 0; e0 < 64; e0 += 4) {
        ull w01[4], w23[4];
#pragma unroll
        for (int t = 0; t < 4; t++) {
            float4 w = *reinterpret_cast<const float4*>(Wp + (e0 + t) * 64);
            w01[t] = pack2(w.x, w.y);
            w23[t] = pack2(w.z, w.w);
        }
#pragma unroll
        for (int i = 0; i < 4; i++) {
            float4 a = *reinterpret_cast<const float4*>(Arow + i * XS_STRIDE + e0);
            ull ax;
            ax = pack2(a.x, a.x); fma2(a01[i], w01[0], ax); fma2(a23[i], w23[0], ax);
            ax = pack2(a.y, a.y); fma2(a01[i], w01[1], ax); fma2(a23[i], w23[1], ax);
            ax = pack2(a.z, a.z); fma2(a01[i], w01[2], ax); fma2(a23[i], w23[2], ax);
            ax = pack2(a.w, a.w); fma2(a01[i], w01[3], ax); fma2(a23[i], w23[3], ax);
        }
    }
#pragma unroll
    for (int i = 0; i < 4; i++) {
        float4 v;
        unpack2(a01[i], v.x, v.y);
        unpack2(a23[i], v.z, v.w);
        epi(rb * 4 + i, cb * 4, v);
    }
}

// ---------- GEMM [64 x 64] * [64 x 96] (final projection), W stride 96 ----------
// 256 threads: rb = tid>>4 (4 rows), cb = tid&15 -> 6 cols at cb*6
__device__ __forceinline__ void gemm96(const float* __restrict__ A,
                                       const float* __restrict__ W,
                                       const float* __restrict__ bias,
                                       float* __restrict__ outbase) {
    const int tid = threadIdx.x;
    const int cb = tid & 15, rb = tid >> 4;
    const int c0 = cb * 6;
    ull acc[4][3];
#pragma unroll
    for (int i = 0; i < 4; i++)
#pragma unroll
        for (int j = 0; j < 3; j++) acc[i][j] = 0ull;
    const float* Arow = A + rb * 4 * XS_STRIDE;
    const float* Wp = W + c0;
#pragma unroll 4
    for (int e0 = 0; e0 < 64; e0 += 4) {
        ull w[4][3];
#pragma unroll
        for (int t = 0; t < 4; t++) {
            const float* wr = Wp + (e0 + t) * 96;
            float2 wA = *reinterpret_cast<const float2*>(wr + 0);
            float2 wB = *reinterpret_cast<const float2*>(wr + 2);
            float2 wC = *reinterpret_cast<const float2*>(wr + 4);
            w[t][0] = pack2(wA.x, wA.y);
            w[t][1] = pack2(wB.x, wB.y);
            w[t][2] = pack2(wC.x, wC.y);
        }
#pragma unroll
        for (int i = 0; i < 4; i++) {
            float4 a = *reinterpret_cast<const float4*>(Arow + i * XS_STRIDE + e0);
            ull ax;
            ax = pack2(a.x, a.x); fma2(acc[i][0], w[0][0], ax); fma2(acc[i][1], w[0][1], ax); fma2(acc[i][2], w[0][2], ax);
            ax = pack2(a.y, a.y); fma2(acc[i][0], w[1][0], ax); fma2(acc[i][1], w[1][1], ax); fma2(acc[i][2], w[1][2], ax);
            ax = pack2(a.z, a.z); fma2(acc[i][0], w[2][0], ax); fma2(acc[i][1], w[2][1], ax); fma2(acc[i][2], w[2][2], ax);
            ax = pack2(a.w, a.w); fma2(acc[i][0], w[3][0], ax); fma2(acc[i][1], w[3][1], ax); fma2(acc[i][2], w[3][2], ax);
        }
    }
    float2 bA = *reinterpret_cast<const float2*>(bias + c0 + 0);
    float2 bB = *reinterpret_cast<const float2*>(bias + c0 + 2);
    float2 bC = *reinterpret_cast<const float2*>(bias + c0 + 4);
#pragma unroll
    for (int i = 0; i < 4; i++) {
        int r = rb * 4 + i;
        float* orow = outbase + (size_t)r * VOCAB + c0;
        float v0, v1;
        unpack2(acc[i][0], v0, v1);
        *reinterpret_cast<float2*>(orow + 0) = make_float2(v0 + bA.x, v1 + bA.y);
        unpack2(acc[i][1], v0, v1);
        *reinterpret_cast<float2*>(orow + 2) = make_float2(v0 + bB.x, v1 + bB.y);
        unpack2(acc[i][2], v0, v1);
        *reinterpret_cast<float2*>(orow + 4) = make_float2(v0 + bC.x, v1 + bC.y);
    }
}

// ---------- LayerNorm over 64 cols, 4 threads per row, 16 cols each ----------
__device__ __forceinline__ void layer_norm(float* xs, const float* g, const float* b) {
    const int tid = threadIdx.x;
    const int r = tid >> 2, p = tid & 3;
    float* base = xs + r * XS_STRIDE + p * 16;
    float4 v[4];
    float s = 0.f, s2 = 0.f;
#pragma unroll
    for (int j = 0; j < 4; j++) {
        v[j] = *reinterpret_cast<const float4*>(base + j * 4);
        s += v[j].x + v[j].y + v[j].z + v[j].w;
        s2 += v[j].x * v[j].x + v[j].y * v[j].y + v[j].z * v[j].z + v[j].w * v[j].w;
    }
    s  += __shfl_xor_sync(0xffffffffu, s, 1, 4);
    s2 += __shfl_xor_sync(0xffffffffu, s2, 1, 4);
    s  += __shfl_xor_sync(0xffffffffu, s, 2, 4);
    s2 += __shfl_xor_sync(0xffffffffu, s2, 2, 4);
    float mean = s * (1.f / 64.f);
    float var = s2 * (1.f / 64.f) - mean * mean;
    float rstd = rsqrtf(var + 1e-5f);
#pragma unroll
    for (int j = 0; j < 4; j++) {
        int c = p * 16 + j * 4;
        float4 gg = *reinterpret_cast<const float4*>(g + c);
        float4 bb = *reinterpret_cast<const float4*>(b + c);
        float4 o;
        o.x = (v[j].x - mean) * rstd * gg.x + bb.x;
        o.y = (v[j].y - mean) * rstd * gg.y + bb.y;
        o.z = (v[j].z - mean) * rstd * gg.z + bb.z;
        o.w = (v[j].w - mean) * rstd * gg.w + bb.w;
        *reinterpret_cast<float4*>(base + j * 4) = o;
    }
}

// Shared memory layout (floats)
#define SM_XS   0
#define SM_TS   (SM_XS + ROWS * XS_STRIDE)        // 4352
#define SM_WS   (SM_TS + ROWS * XS_STRIDE)        // 8704
#define SM_QS   (SM_WS + 6144)                    // 14848
#define SM_KS   (SM_QS + 4096)                    // 18944
#define SM_VS   (SM_KS + 4096)                    // 23040
#define SM_LNG  (SM_VS + 4096)                    // 27136
#define SM_LNB  (SM_LNG + 64)                     // 27200
#define SM_FLOATS (SM_LNB + 64)                   // 27264
#define SMEM_BYTES (SM_FLOATS * 4)                // 109,056 B

__global__ void __launch_bounds__(NTHREADS, 2)
bert_fused_kernel(const int* __restrict__ data,
                  const float* __restrict__ tok_emb,
                  const float* __restrict__ pos_emb,
                  const float* __restrict__ Wq,
                  const float* __restrict__ Wk,
                  const float* __restrict__ Wv,
                  const float* __restrict__ Wo,
                  const float* __restrict__ bo,
                  const float* __restrict__ ln1g,
                  const float* __restrict__ ln1b,
                  const float* __restrict__ ln2g,
                  const float* __restrict__ ln2b,
                  const float* __restrict__ W1,
                  const float* __restrict__ b1,
                  const float* __restrict__ W2,
                  const float* __restrict__ b2,
                  const float* __restrict__ Wout,
                  const float* __restrict__ bout,
                  float* __restrict__ out) {
    extern __shared__ float sm[];
    float* xs = sm + SM_XS;
    float* ts = sm + SM_TS;
    float* ws = sm + SM_WS;
    float* qs = sm + SM_QS;
    float* ks_ = sm + SM_KS;
    float* vs = sm + SM_VS;
    float* lng = sm + SM_LNG;
    float* lnb = sm + SM_LNB;

    const int tid = threadIdx.x;
    const int blk = blockIdx.x;

    // ---------------- embedding
    {
        const int e2 = (tid & 31) * 2;
        const int r0 = tid >> 5;             // 8 row groups
#pragma unroll
        for (int it = 0; it < 8; ++it) {
            int r = it * 8 + r0;
            int b = blk * G + (r >> 4);
            int t = r & 15;
            int tok = data[b * TT + t];
            float2 te = *reinterpret_cast<const float2*>(tok_emb + tok * EE + e2);
            float2 pe = *reinterpret_cast<const float2*>(pos_emb + t * EE + e2);
            *reinterpret_cast<float2*>(xs + r * XS_STRIDE + e2) =
                make_float2(te.x + pe.x, te.y + pe.y);
        }
    }
    __syncthreads();

    for (int l = 0; l < LL; l++) {
        // ---------------- QKV projections
#pragma unroll
        for (int m = 0; m < 3; m++) {
            const float* wsrc = (m == 0) ? (Wq + l * 4096)
                              : (m == 1) ? (Wk + l * 4096)
                                         : (Wv + l * 4096);
            float* dst = (m == 0) ? qs : (m == 1) ? ks_ : vs;
            {
                float4* ws4 = reinterpret_cast<float4*>(ws);
                for (int idx = tid; idx < 1024; idx += NTHREADS) {
                    int e = idx >> 4, cq = idx & 15;
                    ws4[idx] = *reinterpret_cast<const float4*>(
                        wsrc + ((cq >> 2) << 10) + e * 16 + ((cq & 3) << 2));
                }
            }
            __syncthreads();
            gemm64(xs, ws, [&](int r, int c0, float4 v) {
                float* d = dst + ((((r >> 4) << 2) + (c0 >> 4)) << 8) +
                           ((r & 15) << 4) + (c0 & 15);
                *reinterpret_cast<float4*>(d) = v;
            });
            __syncthreads();
        }

        // ---------------- attention: one thread per (g,h,t), 256 items
        {
            const int g = tid >> 6, h = (tid >> 4) & 3, t = tid & 15;
            const int gh = (g << 2) + h;
            const float4* q4 = reinterpret_cast<const float4*>(qs + (gh << 8) + (t << 4));
            const float* kb = ks_ + (gh << 8);
            const float* vb = vs + (gh << 8);
            float4 qa = q4[0], qb = q4[1], qc = q4[2], qd = q4[3];
            float p[16];
            float mx = -1e30f;
#pragma unroll
            for (int s = 0; s < 16; s++) {
                const float4* k4 = reinterpret_cast<const float4*>(kb + (s << 4));
                float4 ka = k4[0], kb2 = k4[1], kc = k4[2], kd = k4[3];
                float acc = qa.x * ka.x + qa.y * ka.y + qa.z * ka.z + qa.w * ka.w
                          + qb.x * kb2.x + qb.y * kb2.y + qb.z * kb2.z + qb.w * kb2.w
                          + qc.x * kc.x + qc.y * kc.y + qc.z * kc.z + qc.w * kc.w
                          + qd.x * kd.x + qd.y * kd.y + qd.z * kd.z + qd.w * kd.w;
                acc *= 0.25f;
                p[s] = acc;
                mx = fmaxf(mx, acc);
            }
            float sum = 0.f;
#pragma unroll
            for (int s = 0; s < 16; s++) { p[s] = __expf(p[s] - mx); sum += p[s]; }
            float inv = 1.f / sum;
            float4 oa = make_float4(0, 0, 0, 0), ob = oa, oc = oa, od = oa;
#pragma unroll
            for (int s = 0; s < 16; s++) {
                float ps = p[s];
                const float4* v4 = reinterpret_cast<const float4*>(vb + (s << 4));
                float4 va = v4[0], vb2 = v4[1], vc = v4[2], vd = v4[3];
                oa.x += ps * va.x; oa.y += ps * va.y; oa.z += ps * va.z; oa.w += ps * va.w;
                ob.x += ps * vb2.x; ob.y += ps * vb2.y; ob.z += ps * vb2.z; ob.w += ps * vb2.w;
                oc.x += ps * vc.x; oc.y += ps * vc.y; oc.z += ps * vc.z; oc.w += ps * vc.w;
                od.x += ps * vd.x; od.y += ps * vd.y; od.z += ps * vd.z; od.w += ps * vd.w;
            }
            const int r = (g << 4) + t;
            float* trow = ts + r * XS_STRIDE + (h << 4);
            oa.x *= inv; oa.y *= inv; oa.z *= inv; oa.w *= inv;
            ob.x *= inv; ob.y *= inv; ob.z *= inv; ob.w *= inv;
            oc.x *= inv; oc.y *= inv; oc.z *= inv; oc.w *= inv;
            od.x *= inv; od.y *= inv; od.z *= inv; od.w *= inv;
            reinterpret_cast<float4*>(trow)[0] = oa;
            reinterpret_cast<float4*>(trow)[1] = ob;
            reinterpret_cast<float4*>(trow)[2] = oc;
            reinterpret_cast<float4*>(trow)[3] = od;
        }
        __syncthreads();

        // ---------------- output projection + residual
        {
            const float4* src4 = reinterpret_cast<const float4*>(Wo + l * 4096);
            float4* ws4 = reinterpret_cast<float4*>(ws);
            for (int idx = tid; idx < 1024; idx += NTHREADS) ws4[idx] = src4[idx];
        }
        __syncthreads();
        {
            const float* bop = bo + l * 64;
            gemm64(ts, ws, [&](int r, int c0, float4 v) {
                float4 bb = *reinterpret_cast<const float4*>(bop + c0);
                float4 x0 = *reinterpret_cast<const float4*>(xs + r * XS_STRIDE + c0);
                v.x += bb.x + x0.x; v.y += bb.y + x0.y;
                v.z += bb.z + x0.z; v.w += bb.w + x0.w;
                *reinterpret_cast<float4*>(xs + r * XS_STRIDE + c0) = v;
            });
        }
        __syncthreads();

        // ---------------- LN1
        if (tid < 64) { lng[tid] = ln1g[l * 64 + tid]; lnb[tid] = ln1b[l * 64 + tid]; }
        __syncthreads();
        layer_norm(xs, lng, lnb);
        __syncthreads();

        // ---------------- FF1: ts = relu(xs @ W1 + b1)
        {
            const float4* src4 = reinterpret_cast<const float4*>(W1 + l * 4096);
            float4* ws4 = reinterpret_cast<float4*>(ws);
            for (int idx = tid; idx < 1024; idx += NTHREADS) ws4[idx] = src4[idx];
        }
        __syncthreads();
        {
            const float* bp = b1 + l * 64;
            gemm64(xs, ws, [&](int r, int c0, float4 v) {
                float4 bb = *reinterpret_cast<const float4*>(bp + c0);
                v.x = fmaxf(v.x + bb.x, 0.f); v.y = fmaxf(v.y + bb.y, 0.f);
                v.z = fmaxf(v.z + bb.z, 0.f); v.w = fmaxf(v.w + bb.w, 0.f);
                *reinterpret_cast<float4*>(ts + r * XS_STRIDE + c0) = v;
            });
        }
        __syncthreads();

        // ---------------- FF2: xs = ts @ W2 + b2 + xs
        {
            const float4* src4 = reinterpret_cast<const float4*>(W2 + l * 4096);
            float4* ws4 = reinterpret_cast<float4*>(ws);
            for (int idx = tid; idx < 1024; idx += NTHREADS) ws4[idx] = src4[idx];
        }
        __syncthreads();
        {
            const float* bp = b2 + l * 64;
            gemm64(ts, ws, [&](int r, int c0, float4 v) {
                float4 bb = *reinterpret_cast<const float4*>(bp + c0);
                float4 x0 = *reinterpret_cast<const float4*>(xs + r * XS_STRIDE + c0);
                v.x += bb.x + x0.x; v.y += bb.y + x0.y;
                v.z += bb.z + x0.z; v.w += bb.w + x0.w;
                *reinterpret_cast<float4*>(xs + r * XS_STRIDE + c0) = v;
            });
        }
        __syncthreads();

        // ---------------- LN2
        if (tid < 64) { lng[tid] = ln2g[l * 64 + tid]; lnb[tid] = ln2b[l * 64 + tid]; }
        __syncthreads();
        layer_norm(xs, lng, lnb);
        __syncthreads();
    }

    // ---------------- final projection
    {
        const float4* src4 = reinterpret_cast<const float4*>(Wout);
        float4* ws4 = reinterpret_cast<float4*>(ws);
        for (int idx = tid; idx < 1536; idx += NTHREADS) ws4[idx] = src4[idx];
    }
    __syncthreads();
    gemm96(xs, ws, bout, out + (size_t)blk * ROWS * VOCAB);
}

extern "C" void kernel_launch(void* const* d_in, const int* in_sizes, int n_in,
                              void* d_out, int out_size) {
    const int*   data    = (const int*)d_in[0];
    const float* tok_emb = (const float*)d_in[1];
    const float* pos_emb = (const float*)d_in[2];
    const float* Wq      = (const float*)d_in[3];
    const float* Wk      = (const float*)d_in[4];
    const float* Wv      = (const float*)d_in[5];
    const float* Wo      = (const float*)d_in[6];
    const float* bo      = (const float*)d_in[7];
    const float* ln1g    = (const float*)d_in[8];
    const float* ln1b    = (const float*)d_in[9];
    const float* ln2g    = (const float*)d_in[10];
    const float* ln2b    = (const float*)d_in[11];
    const float* W1      = (const float*)d_in[12];
    const float* b1      = (const float*)d_in[13];
    const float* W2      = (const float*)d_in[14];
    const float* b2      = (const float*)d_in[15];
    const float* Wout    = (const float*)d_in[16];
    const float* bout    = (const float*)d_in[17];
    float* out = (float*)d_out;

    cudaFuncSetAttribute(bert_fused_kernel,
                         cudaFuncAttributeMaxDynamicSharedMemorySize, SMEM_BYTES);
    bert_fused_kernel<<<BB / G, NTHREADS, SMEM_BYTES>>>(
        data, tok_emb, pos_emb, Wq, Wk, Wv, Wo, bo,
        ln1g, ln1b, ln2g, ln2b, W1, b1, W2, b2, Wout, bout, out);
}

// round 5
// speedup vs baseline: 1.6272x; 1.6272x over previous
#include <cuda_runtime.h>
#include <cuda_bf16.h>
#include <cstdint>

// Problem constants
#define VOCAB 96
#define TT 16
#define EE 64
#define HH 4
#define KK 16
#define LL 4
#define BB 16384

#define G 4                 // sequences per CTA
#define ROWS (G*TT)         // 64 activation rows per CTA
#define STR 64              // row stride (floats) for all 64-wide buffers
#define NTHREADS 128

typedef unsigned long long ull;

// ---------- packed f32x2 helpers ----------
__device__ __forceinline__ ull pack2(float x, float y) {
    ull r;
    asm("mov.b64 %0, {%1, %2};" : "=l"(r) : "r"(__float_as_uint(x)), "r"(__float_as_uint(y)));
    return r;
}
__device__ __forceinline__ void unpack2(ull p, float& x, float& y) {
    unsigned int a, b;
    asm("mov.b64 {%0, %1}, %2;" : "=r"(a), "=r"(b) : "l"(p));
    x = __uint_as_float(a); y = __uint_as_float(b);
}
__device__ __forceinline__ void fma2(ull& d, ull a, ull b) {
    asm("fma.rn.f32x2 %0, %1, %2, %3;" : "=l"(d) : "l"(a), "l"(b), "l"(d));
}

// ---------- GEMM [64 x 64] * [64 x 64]: A stride 64, W stride 64 ----------
// 128 threads: rb = tid>>4 (8 rows each), cb = tid&15 (4 cols each).
// epi(r, c0, float4) once per output row-quad.
template <class F>
__device__ __forceinline__ void gemm64(const float* __restrict__ A,
                                       const float* __restrict__ W, F epi) {
    const int tid = threadIdx.x;
    const int cb = tid & 15, rb = tid >> 4;
    ull a01[8], a23[8];
#pragma unroll
    for (int i = 0; i < 8; i++) { a01[i] = 0ull; a23[i] = 0ull; }
    const float* Arow = A + rb * 8 * STR;
    const float* Wp = W + cb * 4;
#pragma unroll 2
    for (int e0 = 0; e0 < 64; e0 += 4) {
        ull w01[4], w23[4];
#pragma unroll
        for (int t = 0; t < 4; t++) {
            float4 w = *reinterpret_cast<const float4*>(Wp + (e0 + t) * 64);
            w01[t] = pack2(w.x, w.y);
            w23[t] = pack2(w.z, w.w);
        }
#pragma unroll
        for (int i = 0; i < 8; i++) {
            float4 a = *reinterpret_cast<const float4*>(Arow + i * STR + e0);
            ull ax;
            ax = pack2(a.x, a.x); fma2(a01[i], w01[0], ax); fma2(a23[i], w23[0], ax);
            ax = pack2(a.y, a.y); fma2(a01[i], w01[1], ax); fma2(a23[i], w23[1], ax);
            ax = pack2(a.z, a.z); fma2(a01[i], w01[2], ax); fma2(a23[i], w23[2], ax);
            ax = pack2(a.w, a.w); fma2(a01[i], w01[3], ax); fma2(a23[i], w23[3], ax);
        }
    }
#pragma unroll
    for (int i = 0; i < 8; i++) {
        float4 v;
        unpack2(a01[i], v.x, v.y);
        unpack2(a23[i], v.z, v.w);
        epi(rb * 8 + i, cb * 4, v);
    }
}

// ---------- GEMM [64 x 64] * [64 x 96] (final projection), W stride 96 ----------
__device__ __forceinline__ void gemm96(const float* __restrict__ A,
                                       const float* __restrict__ W,
                                       const float* __restrict__ bias,
                                       float* __restrict__ outbase) {
    const int tid = threadIdx.x;
    const int cb = tid & 15, rb = tid >> 4;
    const int c0 = cb * 6;
    ull acc[8][3];
#pragma unroll
    for (int i = 0; i < 8; i++)
#pragma unroll
        for (int j = 0; j < 3; j++) acc[i][j] = 0ull;
    const float* Arow = A + rb * 8 * STR;
    const float* Wp = W + c0;
#pragma unroll 2
    for (int e0 = 0; e0 < 64; e0 += 4) {
        ull w[4][3];
#pragma unroll
        for (int t = 0; t < 4; t++) {
            const float* wr = Wp + (e0 + t) * 96;
            float2 wA = *reinterpret_cast<const float2*>(wr + 0);
            float2 wB = *reinterpret_cast<const float2*>(wr + 2);
            float2 wC = *reinterpret_cast<const float2*>(wr + 4);
            w[t][0] = pack2(wA.x, wA.y);
            w[t][1] = pack2(wB.x, wB.y);
            w[t][2] = pack2(wC.x, wC.y);
        }
#pragma unroll
        for (int i = 0; i < 8; i++) {
            float4 a = *reinterpret_cast<const float4*>(Arow + i * STR + e0);
            ull ax;
            ax = pack2(a.x, a.x); fma2(acc[i][0], w[0][0], ax); fma2(acc[i][1], w[0][1], ax); fma2(acc[i][2], w[0][2], ax);
            ax = pack2(a.y, a.y); fma2(acc[i][0], w[1][0], ax); fma2(acc[i][1], w[1][1], ax); fma2(acc[i][2], w[1][2], ax);
            ax = pack2(a.z, a.z); fma2(acc[i][0], w[2][0], ax); fma2(acc[i][1], w[2][1], ax); fma2(acc[i][2], w[2][2], ax);
            ax = pack2(a.w, a.w); fma2(acc[i][0], w[3][0], ax); fma2(acc[i][1], w[3][1], ax); fma2(acc[i][2], w[3][2], ax);
        }
    }
    float2 bA = *reinterpret_cast<const float2*>(bias + c0 + 0);
    float2 bB = *reinterpret_cast<const float2*>(bias + c0 + 2);
    float2 bC = *reinterpret_cast<const float2*>(bias + c0 + 4);
#pragma unroll
    for (int i = 0; i < 8; i++) {
        int r = rb * 8 + i;
        float* orow = outbase + (size_t)r * VOCAB + c0;
        float v0, v1;
        unpack2(acc[i][0], v0, v1);
        *reinterpret_cast<float2*>(orow + 0) = make_float2(v0 + bA.x, v1 + bA.y);
        unpack2(acc[i][1], v0, v1);
        *reinterpret_cast<float2*>(orow + 2) = make_float2(v0 + bB.x, v1 + bB.y);
        unpack2(acc[i][2], v0, v1);
        *reinterpret_cast<float2*>(orow + 4) = make_float2(v0 + bC.x, v1 + bC.y);
    }
}

// ---------- LayerNorm over 64 cols, 2 threads per row, 32 cols each ----------
__device__ __forceinline__ void layer_norm(float* xs, const float* g, const float* b) {
    const int tid = threadIdx.x;
    const int r = tid >> 1, p = tid & 1;
    float* base = xs + r * STR + p * 32;
    float4 v[8];
    float s = 0.f, s2 = 0.f;
#pragma unroll
    for (int j = 0; j < 8; j++) {
        v[j] = *reinterpret_cast<const float4*>(base + j * 4);
        s += v[j].x + v[j].y + v[j].z + v[j].w;
        s2 += v[j].x * v[j].x + v[j].y * v[j].y + v[j].z * v[j].z + v[j].w * v[j].w;
    }
    s  += __shfl_xor_sync(0xffffffffu, s, 1, 2);
    s2 += __shfl_xor_sync(0xffffffffu, s2, 1, 2);
    float mean = s * (1.f / 64.f);
    float var = s2 * (1.f / 64.f) - mean * mean;
    float rstd = rsqrtf(var + 1e-5f);
#pragma unroll
    for (int j = 0; j < 8; j++) {
        int c = p * 32 + j * 4;
        float4 gg = *reinterpret_cast<const float4*>(g + c);
        float4 bb = *reinterpret_cast<const float4*>(b + c);
        float4 o;
        o.x = (v[j].x - mean) * rstd * gg.x + bb.x;
        o.y = (v[j].y - mean) * rstd * gg.y + bb.y;
        o.z = (v[j].z - mean) * rstd * gg.z + bb.z;
        o.w = (v[j].w - mean) * rstd * gg.w + bb.w;
        *reinterpret_cast<float4*>(base + j * 4) = o;
    }
}

// ---------- staging helpers ----------
__device__ __forceinline__ void stage_plain(float* dst, const float* src) {
    // 4096 floats, [E][E] row-major
    float4* d4 = reinterpret_cast<float4*>(dst);
    const float4* s4 = reinterpret_cast<const float4*>(src);
    const int tid = threadIdx.x;
#pragma unroll
    for (int i = 0; i < 8; i++) d4[tid + i * NTHREADS] = s4[tid + i * NTHREADS];
}
__device__ __forceinline__ void stage_qkv(float* dst, const float* src) {
    // rearrange [h][e][k] -> [e][h*16+k], 4096 floats
    float4* d4 = reinterpret_cast<float4*>(dst);
    const int tid = threadIdx.x;
#pragma unroll
    for (int i = 0; i < 8; i++) {
        int idx = tid + i * NTHREADS;
        int e = idx >> 4, cq = idx & 15;
        d4[idx] = *reinterpret_cast<const float4*>(
            src + ((cq >> 2) << 10) + e * 16 + ((cq & 3) << 2));
    }
}

// Shared memory layout (floats)
#define SM_XS   0
#define SM_WS0  (SM_XS + 4096)       // 4096
#define SM_WS1  (SM_WS0 + 4096)      // 8192
#define SM_Q    (SM_WS1 + 4096)      // 12288
#define SM_K    (SM_Q + 4096)        // 16384
#define SM_V    (SM_K + 4096)        // 20480
#define SM_LN   (SM_V + 4096)        // 24576  (256 floats: ln1g ln1b ln2g ln2b)
#define SM_FLOATS (SM_LN + 256)      // 24832
#define SMEM_BYTES (SM_FLOATS * 4)   // 99,328 B

__global__ void __launch_bounds__(NTHREADS, 2)
bert_fused_kernel(const int* __restrict__ data,
                  const float* __restrict__ tok_emb,
                  const float* __restrict__ pos_emb,
                  const float* __restrict__ Wq,
                  const float* __restrict__ Wk,
                  const float* __restrict__ Wv,
                  const float* __restrict__ Wo,
                  const float* __restrict__ bo,
                  const float* __restrict__ ln1g,
                  const float* __restrict__ ln1b,
                  const float* __restrict__ ln2g,
                  const float* __restrict__ ln2b,
                  const float* __restrict__ W1,
                  const float* __restrict__ b1,
                  const float* __restrict__ W2,
                  const float* __restrict__ b2,
                  const float* __restrict__ Wout,
                  const float* __restrict__ bout,
                  float* __restrict__ out) {
    extern __shared__ float sm[];
    float* xs  = sm + SM_XS;
    float* ws0 = sm + SM_WS0;
    float* ws1 = sm + SM_WS1;
    float* qb  = sm + SM_Q;
    float* kb  = sm + SM_K;
    float* vb  = sm + SM_V;
    float* ln  = sm + SM_LN;

    const int tid = threadIdx.x;
    const int blk = blockIdx.x;

    // ---------------- embedding: xs[r][e] = tok_emb[tok][e] + pos_emb[t][e]
    {
        const int e2 = (tid & 31) * 2;
        const int r0 = tid >> 5;             // 0..3
#pragma unroll
        for (int it = 0; it < 16; ++it) {
            int r = it * 4 + r0;
            int b = blk * G + (r >> 4);
            int t = r & 15;
            int tok = data[b * TT + t];
            float2 te = *reinterpret_cast<const float2*>(tok_emb + tok * EE + e2);
            float2 pe = *reinterpret_cast<const float2*>(pos_emb + t * EE + e2);
            *reinterpret_cast<float2*>(xs + r * STR + e2) =
                make_float2(te.x + pe.x, te.y + pe.y);
        }
    }
    __syncthreads();   // S0: xs ready

    for (int l = 0; l < LL; l++) {
        // -------- stage Wq, Wk, LN params
        stage_qkv(ws0, Wq + l * 4096);
        stage_qkv(ws1, Wk + l * 4096);
        ln[tid]       = (tid < 64) ? ln1g[l * 64 + tid] : ln1b[l * 64 + tid - 64];
        ln[128 + tid] = (tid < 64) ? ln2g[l * 64 + tid] : ln2b[l * 64 + tid - 64];
        __syncthreads();   // S1

        // -------- gemm Q, gemm K (disjoint outputs, no sync between)
        gemm64(xs, ws0, [&](int r, int c0, float4 v) {
            *reinterpret_cast<float4*>(qb + r * STR + c0) = v;
        });
        gemm64(xs, ws1, [&](int r, int c0, float4 v) {
            *reinterpret_cast<float4*>(kb + r * STR + c0) = v;
        });
        __syncthreads();   // S2: q,k ready; ws0/ws1 free

        // -------- stage Wv, Wo
        stage_qkv(ws0, Wv + l * 4096);
        stage_plain(ws1, Wo + l * 4096);
        __syncthreads();   // S3

        // -------- gemm V
        gemm64(xs, ws0, [&](int r, int c0, float4 v) {
            *reinterpret_cast<float4*>(vb + r * STR + c0) = v;
        });
        __syncthreads();   // S4: v ready; ws0 free

        // -------- stage W1 (overlaps attention) + attention
        stage_plain(ws0, W1 + l * 4096);
        {
#pragma unroll
            for (int half = 0; half < 2; half++) {
                const int item = tid + half * NTHREADS;
                const int g = item >> 6, h = (item >> 4) & 3, t = item & 15;
                const int r = (g << 4) + t;
                const int ch = h << 4;
                const float4* q4 = reinterpret_cast<const float4*>(qb + r * STR + ch);
                float4 qa = q4[0], qbv = q4[1], qc = q4[2], qd = q4[3];
                const float* kbase = kb + (g << 10) + ch;   // row g*16, col h*16
                const float* vbase = vb + (g << 10) + ch;
                float p[16];
                float mx = -1e30f;
#pragma unroll
                for (int s = 0; s < 16; s++) {
                    const float4* k4 = reinterpret_cast<const float4*>(kbase + (s << 6));
                    float4 ka = k4[0], kb2 = k4[1], kc = k4[2], kd = k4[3];
                    float acc = qa.x * ka.x + qa.y * ka.y + qa.z * ka.z + qa.w * ka.w
                              + qbv.x * kb2.x + qbv.y * kb2.y + qbv.z * kb2.z + qbv.w * kb2.w
                              + qc.x * kc.x + qc.y * kc.y + qc.z * kc.z + qc.w * kc.w
                              + qd.x * kd.x + qd.y * kd.y + qd.z * kd.z + qd.w * kd.w;
                    acc *= 0.25f;
                    p[s] = acc;
                    mx = fmaxf(mx, acc);
                }
                float sum = 0.f;
#pragma unroll
                for (int s = 0; s < 16; s++) { p[s] = __expf(p[s] - mx); sum += p[s]; }
                float inv = 1.f / sum;
                float4 oa = make_float4(0, 0, 0, 0), ob = oa, oc = oa, od = oa;
#pragma unroll
                for (int s = 0; s < 16; s++) {
                    float ps = p[s];
                    const float4* v4 = reinterpret_cast<const float4*>(vbase + (s << 6));
                    float4 va = v4[0], vb2 = v4[1], vc = v4[2], vd = v4[3];
                    oa.x += ps * va.x; oa.y += ps * va.y; oa.z += ps * va.z; oa.w += ps * va.w;
                    ob.x += ps * vb2.x; ob.y += ps * vb2.y; ob.z += ps * vb2.z; ob.w += ps * vb2.w;
                    oc.x += ps * vc.x; oc.y += ps * vc.y; oc.z += ps * vc.z; oc.w += ps * vc.w;
                    od.x += ps * vd.x; od.y += ps * vd.y; od.z += ps * vd.z; od.w += ps * vd.w;
                }
                // write o back into this item's own q slot (exclusive)
                float4* orow = reinterpret_cast<float4*>(qb + r * STR + ch);
                oa.x *= inv; oa.y *= inv; oa.z *= inv; oa.w *= inv;
                ob.x *= inv; ob.y *= inv; ob.z *= inv; ob.w *= inv;
                oc.x *= inv; oc.y *= inv; oc.z *= inv; oc.w *= inv;
                od.x *= inv; od.y *= inv; od.z *= inv; od.w *= inv;
                orow[0] = oa; orow[1] = ob; orow[2] = oc; orow[3] = od;
            }
        }
        __syncthreads();   // S5: o(in qb) ready, W1 staged

        // -------- output projection + residual: xs += o @ Wo + bo
        {
            const float* bop = bo + l * 64;
            gemm64(qb, ws1, [&](int r, int c0, float4 v) {
                float4 bb = *reinterpret_cast<const float4*>(bop + c0);
                float4 x0 = *reinterpret_cast<const float4*>(xs + r * STR + c0);
                v.x += bb.x + x0.x; v.y += bb.y + x0.y;
                v.z += bb.z + x0.z; v.w += bb.w + x0.w;
                *reinterpret_cast<float4*>(xs + r * STR + c0) = v;
            });
        }
        __syncthreads();   // S6: xs updated; ws1 free

        // -------- LN1 + stage W2 (overlap)
        stage_plain(ws1, W2 + l * 4096);
        layer_norm(xs, ln, ln + 64);
        __syncthreads();   // S7

        // -------- FF1: kb = relu(xs @ W1 + b1)
        {
            const float* bp = b1 + l * 64;
            gemm64(xs, ws0, [&](int r, int c0, float4 v) {
                float4 bb = *reinterpret_cast<const float4*>(bp + c0);
                v.x = fmaxf(v.x + bb.x, 0.f); v.y = fmaxf(v.y + bb.y, 0.f);
                v.z = fmaxf(v.z + bb.z, 0.f); v.w = fmaxf(v.w + bb.w, 0.f);
                *reinterpret_cast<float4*>(kb + r * STR + c0) = v;
            });
        }
        __syncthreads();   // S8

        // -------- FF2: xs += kb @ W2 + b2
        {
            const float* bp = b2 + l * 64;
            gemm64(kb, ws1, [&](int r, int c0, float4 v) {
                float4 bb = *reinterpret_cast<const float4*>(bp + c0);
                float4 x0 = *reinterpret_cast<const float4*>(xs + r * STR + c0);
                v.x += bb.x + x0.x; v.y += bb.y + x0.y;
                v.z += bb.z + x0.z; v.w += bb.w + x0.w;
                *reinterpret_cast<float4*>(xs + r * STR + c0) = v;
            });
        }
        __syncthreads();   // S9

        // -------- LN2
        layer_norm(xs, ln + 128, ln + 192);
        __syncthreads();   // S10
    }

    // ---------------- final projection: out = xs @ Wout + bout
    {
        // 6144 floats into ws0..ws1 (contiguous 8192 region)
        float4* d4 = reinterpret_cast<float4*>(ws0);
        const float4* s4 = reinterpret_cast<const float4*>(Wout);
#pragma unroll
        for (int i = 0; i < 12; i++) d4[tid + i * NTHREADS] = s4[tid + i * NTHREADS];
    }
    __syncthreads();
    gemm96(xs, ws0, bout, out + (size_t)blk * ROWS * VOCAB);
}

extern "C" void kernel_launch(void* const* d_in, const int* in_sizes, int n_in,
                              void* d_out, int out_size) {
    const int*   data    = (const int*)d_in[0];
    const float* tok_emb = (const float*)d_in[1];
    const float* pos_emb = (const float*)d_in[2];
    const float* Wq      = (const float*)d_in[3];
    const float* Wk      = (const float*)d_in[4];
    const float* Wv      = (const float*)d_in[5];
    const float* Wo      = (const float*)d_in[6];
    const float* bo      = (const float*)d_in[7];
    const float* ln1g    = (const float*)d_in[8];
    const float* ln1b    = (const float*)d_in[9];
    const float* ln2g    = (const float*)d_in[10];
    const float* ln2b    = (const float*)d_in[11];
    const float* W1      = (const float*)d_in[12];
    const float* b1      = (const float*)d_in[13];
    const float* W2      = (const float*)d_in[14];
    const float* b2      = (const float*)d_in[15];
    const float* Wout    = (const float*)d_in[16];
    const float* bout    = (const float*)d_in[17];
    float* out = (float*)d_out;

    cudaFuncSetAttribute(bert_fused_kernel,
                         cudaFuncAttributeMaxDynamicSharedMemorySize, SMEM_BYTES);
    bert_fused_kernel<<<BB / G, NTHREADS, SMEM_BYTES>>>(
        data, tok_emb, pos_emb, Wq, Wk, Wv, Wo, bo,
        ln1g, ln1b, ln2g, ln2b, W1, b1, W2, b2, Wout, bout, out);
}